// round 10
// baseline (speedup 1.0000x reference)
#include <cuda_runtime.h>
#include <cuda_bf16.h>
#include <cstdint>

#define HH 128
#define WW_ 256
#define CDIM 192
#define HDIM 32
#define HIDDEN 768
#define MROWS 131072
#define SHIFT 4

__device__ __nv_bfloat16 g_xw [(size_t)MROWS*CDIM];
__device__ __nv_bfloat16 g_x1w[(size_t)MROWS*CDIM];
__device__ __nv_bfloat16 g_qb [(size_t)MROWS*CDIM];
__device__ __nv_bfloat16 g_kvb[(size_t)MROWS*2*CDIM];
__device__ __nv_bfloat16 g_ao [(size_t)MROWS*CDIM];
__device__ float         g_xo [(size_t)MROWS*CDIM];
__device__ __nv_bfloat16 g_xn2[(size_t)MROWS*CDIM];
__device__ __nv_bfloat16 g_hb [(size_t)MROWS*HIDDEN];
__device__ __nv_bfloat16 g_wq [CDIM*CDIM];
__device__ __nv_bfloat16 g_wkv[2*CDIM*CDIM];
__device__ __nv_bfloat16 g_wp [CDIM*CDIM];
__device__ __nv_bfloat16 g_wf1[HIDDEN*CDIM];
__device__ __nv_bfloat16 g_wf2[CDIM*HIDDEN];

__device__ __forceinline__ uint32_t smem_u32(const void* p){
    uint32_t r; asm("{ .reg .u64 t; cvta.to.shared.u64 t, %1; cvt.u32.u64 %0, t; }":"=r"(r):"l"(p)); return r;
}
__device__ __forceinline__ int win_src_row(int r){
    int b_=r>>6, t=r&63, b=b_>>9, wid=b_&511;
    int h=(((wid>>5)<<3)+(t>>3)+SHIFT)&(HH-1);
    int w=(((wid&31)<<3)+(t&7)+SHIFT)&(WW_-1);
    return (b<<15)+(h<<8)+w;
}
__device__ __forceinline__ float warp_sum(float v){
#pragma unroll
    for(int o=16;o>0;o>>=1) v+=__shfl_xor_sync(0xffffffffu,v,o);
    return v;
}
__device__ __forceinline__ float gelu_exact(float v){ return 0.5f*v*(1.0f+erff(v*0.70710678118654752f)); }
__device__ __forceinline__ uint32_t bf2pack(float lo,float hi){
    uint32_t r; asm("cvt.rn.bf16x2.f32 %0, %1, %2;":"=r"(r):"f"(hi),"f"(lo)); return r;
}
__device__ __forceinline__ void cp_async16(uint32_t dst, const void* src){
    asm volatile("cp.async.cg.shared.global [%0], [%1], 16;"::"r"(dst),"l"(src):"memory");
}
__device__ __forceinline__ void cp_commit(){ asm volatile("cp.async.commit_group;":::"memory"); }
template<int N> __device__ __forceinline__ void cp_wait(){ asm volatile("cp.async.wait_group %0;"::"n"(N):"memory"); }

// ---------------------------------------------------------------------------
// Fused weight prep: all five [K,N]->[N,K] bf16 transposes in ONE launch.
// ---------------------------------------------------------------------------
__global__ void wt_transpose_all(const float* __restrict__ q_w, const float* __restrict__ kv_w,
                                 const float* __restrict__ proj_w, const float* __restrict__ fc1_w,
                                 const float* __restrict__ fc2_w,
                                 __nv_bfloat16* __restrict__ wq, __nv_bfloat16* __restrict__ wkv,
                                 __nv_bfloat16* __restrict__ wp, __nv_bfloat16* __restrict__ wf1,
                                 __nv_bfloat16* __restrict__ wf2){
    int i = blockIdx.x*256+threadIdx.x;
    const float* s; __nv_bfloat16* d; int K, N;
    if      (i < 36864)  { s=q_w;    d=wq;  K=CDIM;   N=CDIM;   }
    else if (i < 110592) { s=kv_w;   d=wkv; K=CDIM;   N=2*CDIM; i-=36864;  }
    else if (i < 147456) { s=proj_w; d=wp;  K=CDIM;   N=CDIM;   i-=110592; }
    else if (i < 294912) { s=fc1_w;  d=wf1; K=CDIM;   N=HIDDEN; i-=147456; }
    else if (i < 442368) { s=fc2_w;  d=wf2; K=HIDDEN; N=CDIM;   i-=294912; }
    else return;
    int n=i/K, k=i-n*K;
    d[i] = __float2bfloat16(s[(size_t)k*N+n]);
}

__global__ void ln1_gather_kernel(const float* __restrict__ x, const float* __restrict__ x1,
                                  const float* __restrict__ g, const float* __restrict__ bb,
                                  __nv_bfloat16* __restrict__ xw, __nv_bfloat16* __restrict__ x1w){
    int r=blockIdx.x, src=win_src_row(r), t=threadIdx.x;
    float v0=x[(size_t)src*CDIM+t], v1=x1[(size_t)src*CDIM+t];
    float s0=warp_sum(v0), q0=warp_sum(v0*v0), s1=warp_sum(v1), q1=warp_sum(v1*v1);
    __shared__ float red[4][6];
    int wp=t>>5, ln=t&31;
    if(ln==0){ red[0][wp]=s0; red[1][wp]=q0; red[2][wp]=s1; red[3][wp]=q1; }
    __syncthreads();
    float S0=0,Q0=0,S1=0,Q1=0;
#pragma unroll
    for(int i=0;i<6;i++){ S0+=red[0][i]; Q0+=red[1][i]; S1+=red[2][i]; Q1+=red[3][i]; }
    const float inv=1.0f/CDIM;
    float m0=S0*inv, m1=S1*inv;
    float r0=rsqrtf(Q0*inv-m0*m0+1e-5f), r1=rsqrtf(Q1*inv-m1*m1+1e-5f);
    float gg=g[t], bv=bb[t];
    xw [(size_t)r*CDIM+t]=__float2bfloat16((v0-m0)*r0*gg+bv);
    x1w[(size_t)r*CDIM+t]=__float2bfloat16((v1-m1)*r1*gg+bv);
}

__global__ void ln2_kernel(const float* __restrict__ x, const float* __restrict__ g,
                           const float* __restrict__ bb, __nv_bfloat16* __restrict__ out){
    int r=blockIdx.x, t=threadIdx.x;
    float v=x[(size_t)r*CDIM+t];
    float s=warp_sum(v), q=warp_sum(v*v);
    __shared__ float red[2][6];
    int wp=t>>5, ln=t&31;
    if(ln==0){ red[0][wp]=s; red[1][wp]=q; }
    __syncthreads();
    float S=0,Q=0;
#pragma unroll
    for(int i=0;i<6;i++){ S+=red[0][i]; Q+=red[1][i]; }
    const float inv=1.0f/CDIM;
    float m=S*inv, rs=rsqrtf(Q*inv-m*m+1e-5f);
    out[(size_t)r*CDIM+t]=__float2bfloat16((v-m)*rs*g[t]+bb[t]);
}

// ---------------------------------------------------------------------------
// HMMA bf16 GEMM: C[M,N] = A[M,K] @ Bw[N,K]^T.  BM=128 BN=64 BK=64, 256 thr,
// 8 warps (4 M x 2 N), warp tile 32x32, mma.m16n8k16.
// R10: 3-stage cp.async pipeline + intra-chunk fragment double-buffering.
// EPI: 0 bias, 1 bias+gelu, 2 bias+scatter+residual, 3 bias+residual.
// ---------------------------------------------------------------------------
#define ABUF 16384
#define BUFB 24576
#define GEMM_SMEM_BYTES (3*BUFB + 1024)

template <int EPI, int OUTBF>
__global__ __launch_bounds__(256)
void gemm_mma(const __nv_bfloat16* __restrict__ A, const __nv_bfloat16* __restrict__ Bw,
              const float* __restrict__ bias, const float* __restrict__ res,
              void* __restrict__ Cv, int M, int N, int K){
    extern __shared__ char dsm[];
    uint32_t base = (smem_u32(dsm)+1023u)&~1023u;

    int tid=threadIdx.x, lane=tid&31, wid=tid>>5;
    int wm=wid&3, wn=wid>>2;
    int m0=blockIdx.x*128, n0=blockIdx.y*64;

    float acc[2][4][4];
#pragma unroll
    for(int a=0;a<2;a++)
#pragma unroll
        for(int b=0;b<4;b++)
#pragma unroll
            for(int c=0;c<4;c++) acc[a][b][c]=0.0f;

    auto stage=[&](int buf,int k0){
        uint32_t sA=base+buf*BUFB, sB=sA+ABUF;
#pragma unroll
        for(int l=0;l<4;l++){           // A: 1024 x 16B
            int i=tid+l*256, rr=i>>3, cc=i&7;
            uint32_t off=rr*128+cc*16;
            cp_async16(sA+(off^((off>>3)&0x70)), A+(size_t)(m0+rr)*K+k0+cc*8);
        }
#pragma unroll
        for(int l=0;l<2;l++){           // B: 512 x 16B
            int i=tid+l*256, rr=i>>3, cc=i&7;
            uint32_t off=rr*128+cc*16;
            cp_async16(sB+(off^((off>>3)&0x70)), Bw+(size_t)(n0+rr)*K+k0+cc*8);
        }
        cp_commit();
    };

    int nch=K>>6;                 // always >= 3 here (K in {192,384,768})
    stage(0,0);
    stage(1,64);

    int buf=0;
    for(int c=0;c<nch;c++){
        if(c+2<nch) stage((buf+2)%3,(c+2)<<6);
        else        cp_commit();               // keep group count uniform
        cp_wait<2>();
        __syncthreads();

        uint32_t sA=base+buf*BUFB, sB=sA+ABUF;

        uint32_t af[2][2][4], bfq[2][4][2];
        auto ldfrag=[&](int kk,int pb){
#pragma unroll
            for(int mt=0;mt<2;mt++){
                int row=wm*32+mt*16+(lane&15);
                uint32_t off=row*128+kk*32+(lane>>4)*16;
                off^=((off>>3)&0x70);
                asm volatile("ldmatrix.sync.aligned.m8n8.x4.shared.b16 {%0,%1,%2,%3}, [%4];"
                    :"=r"(af[pb][mt][0]),"=r"(af[pb][mt][1]),"=r"(af[pb][mt][2]),"=r"(af[pb][mt][3]):"r"(sA+off));
            }
#pragma unroll
            for(int nt=0;nt<4;nt++){
                int rowb=wn*32+nt*8+(lane&7);
                uint32_t off=rowb*128+kk*32+((lane>>3)&1)*16;
                off^=((off>>3)&0x70);
                asm volatile("ldmatrix.sync.aligned.m8n8.x2.shared.b16 {%0,%1}, [%2];"
                    :"=r"(bfq[pb][nt][0]),"=r"(bfq[pb][nt][1]):"r"(sB+off));
            }
        };

        ldfrag(0,0);
#pragma unroll
        for(int kk=0;kk<4;kk++){
            if(kk<3) ldfrag(kk+1,(kk+1)&1);
            int pb=kk&1;
#pragma unroll
            for(int mt=0;mt<2;mt++)
#pragma unroll
                for(int nt=0;nt<4;nt++)
                    asm volatile("mma.sync.aligned.m16n8k16.row.col.f32.bf16.bf16.f32 "
                        "{%0,%1,%2,%3}, {%4,%5,%6,%7}, {%8,%9}, {%0,%1,%2,%3};"
                        :"+f"(acc[mt][nt][0]),"+f"(acc[mt][nt][1]),"+f"(acc[mt][nt][2]),"+f"(acc[mt][nt][3])
                        :"r"(af[pb][mt][0]),"r"(af[pb][mt][1]),"r"(af[pb][mt][2]),"r"(af[pb][mt][3]),
                         "r"(bfq[pb][nt][0]),"r"(bfq[pb][nt][1]));
        }
        __syncthreads();
        buf = (buf+1)%3;
    }

#pragma unroll
    for(int mt=0;mt<2;mt++){
#pragma unroll
        for(int half=0;half<2;half++){
            int row=m0+wm*32+mt*16+(lane>>2)+half*8;
            int orow=(EPI==2)?win_src_row(row):row;
#pragma unroll
            for(int nt=0;nt<4;nt++){
                int col=n0+wn*32+nt*8+(lane&3)*2;
                float v0=acc[mt][nt][half*2+0]+__ldg(bias+col);
                float v1=acc[mt][nt][half*2+1]+__ldg(bias+col+1);
                if(EPI==1){ v0=gelu_exact(v0); v1=gelu_exact(v1); }
                if(EPI==2||EPI==3){
                    const float* rp=res+(size_t)orow*N+col;
                    v0+=rp[0]; v1+=rp[1];
                }
                if(OUTBF){
                    *(uint32_t*)((__nv_bfloat16*)Cv+(size_t)orow*N+col)=bf2pack(v0,v1);
                }else{
                    *(float2*)((float*)Cv+(size_t)orow*N+col)=make_float2(v0,v1);
                }
            }
        }
    }
}

// ---------------------------------------------------------------------------
// Attention: one block per window, 384 thr (6 heads x 64 rows), f32x2 FMA,
// single-pass softmax (scores tiny; mask -100 underflows exp -> 0).
// ---------------------------------------------------------------------------
#define ATTN_SMEM_BYTES 112256

__global__ __launch_bounds__(384)
void attn_kernel(const __nv_bfloat16* __restrict__ q, const __nv_bfloat16* __restrict__ kv,
                 const float* __restrict__ rpb, const float* __restrict__ mask,
                 __nv_bfloat16* __restrict__ ao){
    extern __shared__ char dsm[];
    unsigned long long* K8=(unsigned long long*)dsm;   // [64][96] f32x2
    unsigned long long* V8=K8+64*96;
    __nv_bfloat16* Ms=(__nv_bfloat16*)(V8+64*96);      // [64][66]
    float* Rp=(float*)(Ms+64*66);                      // [1350]

    int win=blockIdx.x, tid=threadIdx.x;
    const __nv_bfloat162* kvb=(const __nv_bfloat162*)(kv+(size_t)win*64*384);
    for(int i=tid;i<64*192;i+=384){
        int row=i/192, p=i-row*192;
        float2 f=__bfloat1622float2(kvb[row*192+p]);
        unsigned long long pk;
        asm("mov.b64 %0,{%1,%2};":"=l"(pk):"r"(__float_as_uint(f.x)),"r"(__float_as_uint(f.y)));
        if(p<96) K8[row*96+p]=pk; else V8[row*96+p-96]=pk;
    }
    const float* mg=mask+(size_t)(win&511)*4096;
    for(int i=tid;i<4096;i+=384) Ms[(i>>6)*66+(i&63)]=__float2bfloat16(mg[i]);
    for(int i=tid;i<1350;i+=384) Rp[i]=rpb[i];

    int h=tid/64, t=tid-h*64;
    unsigned long long q2[16];
    {
        const __nv_bfloat162* qp=(const __nv_bfloat162*)(q+((size_t)win*64+t)*CDIM+h*HDIM);
        const float sc=0.17677669529663688f;
#pragma unroll
        for(int d=0;d<16;d++){
            float2 f=__bfloat1622float2(qp[d]);
            f.x*=sc; f.y*=sc;
            asm("mov.b64 %0,{%1,%2};":"=l"(q2[d]):"r"(__float_as_uint(f.x)),"r"(__float_as_uint(f.y)));
        }
    }
    __syncthreads();

    int i1=t>>3, j1=t&7, kb=h*16;
    unsigned long long od[16];
#pragma unroll
    for(int d=0;d<16;d++) od[d]=0ULL;
    float sum=0.0f;

    for(int m=0;m<64;m++){
        const unsigned long long* kp=K8+m*96+kb;
        unsigned long long a0=0,a1=0,a2=0,a3=0;
#pragma unroll
        for(int d=0;d<16;d+=4){
            asm("fma.rn.f32x2 %0, %1, %2, %0;":"+l"(a0):"l"(q2[d+0]),"l"(kp[d+0]));
            asm("fma.rn.f32x2 %0, %1, %2, %0;":"+l"(a1):"l"(q2[d+1]),"l"(kp[d+1]));
            asm("fma.rn.f32x2 %0, %1, %2, %0;":"+l"(a2):"l"(q2[d+2]),"l"(kp[d+2]));
            asm("fma.rn.f32x2 %0, %1, %2, %0;":"+l"(a3):"l"(q2[d+3]),"l"(kp[d+3]));
        }
        uint32_t lo,hi; float s;
        asm("mov.b64 {%0,%1}, %2;":"=r"(lo),"=r"(hi):"l"(a0)); s =__uint_as_float(lo)+__uint_as_float(hi);
        asm("mov.b64 {%0,%1}, %2;":"=r"(lo),"=r"(hi):"l"(a1)); s+=__uint_as_float(lo)+__uint_as_float(hi);
        asm("mov.b64 {%0,%1}, %2;":"=r"(lo),"=r"(hi):"l"(a2)); s+=__uint_as_float(lo)+__uint_as_float(hi);
        asm("mov.b64 {%0,%1}, %2;":"=r"(lo),"=r"(hi):"l"(a3)); s+=__uint_as_float(lo)+__uint_as_float(hi);

        int ridx=(i1-(m>>3)+7)*15+(j1-(m&7)+7);
        s += Rp[ridx*6+h] + __bfloat162float(Ms[t*66+m]);
        float e=__expf(s);
        sum+=e;
        unsigned long long e2;
        asm("mov.b64 %0,{%1,%1};":"=l"(e2):"r"(__float_as_uint(e)));
        const unsigned long long* vp=V8+m*96+kb;
#pragma unroll
        for(int d=0;d<16;d++)
            asm("fma.rn.f32x2 %0, %1, %2, %0;":"+l"(od[d]):"l"(e2),"l"(vp[d]));
    }
    float inv=1.0f/sum;
    __nv_bfloat162* orow=(__nv_bfloat162*)(ao+((size_t)win*64+t)*CDIM+h*HDIM);
#pragma unroll
    for(int d=0;d<16;d++){
        uint32_t lo,hi;
        asm("mov.b64 {%0,%1}, %2;":"=r"(lo),"=r"(hi):"l"(od[d]));
        orow[d]=__floats2bfloat162_rn(__uint_as_float(lo)*inv,__uint_as_float(hi)*inv);
    }
}

extern "C" void kernel_launch(void* const* d_in, const int* in_sizes, int n_in,
                              void* d_out, int out_size){
    const float* x     =(const float*)d_in[0];
    const float* x1    =(const float*)d_in[1];
    const float* mask  =(const float*)d_in[2];
    const float* n1g   =(const float*)d_in[3];
    const float* n1b   =(const float*)d_in[4];
    const float* q_w   =(const float*)d_in[5];
    const float* q_b   =(const float*)d_in[6];
    const float* kv_w  =(const float*)d_in[7];
    const float* kv_b  =(const float*)d_in[8];
    const float* rpb   =(const float*)d_in[9];
    const float* proj_w=(const float*)d_in[10];
    const float* proj_b=(const float*)d_in[11];
    const float* n2g   =(const float*)d_in[12];
    const float* n2b   =(const float*)d_in[13];
    const float* fc1_w =(const float*)d_in[14];
    const float* fc1_b =(const float*)d_in[15];
    const float* fc2_w =(const float*)d_in[16];
    const float* fc2_b =(const float*)d_in[17];

    __nv_bfloat16 *xw,*x1w,*qb,*kvb,*ao,*xn2,*hb,*wq,*wkv,*wp,*wf1,*wf2;
    float* xo;
    cudaGetSymbolAddress((void**)&xw, g_xw);  cudaGetSymbolAddress((void**)&x1w,g_x1w);
    cudaGetSymbolAddress((void**)&qb, g_qb);  cudaGetSymbolAddress((void**)&kvb,g_kvb);
    cudaGetSymbolAddress((void**)&ao, g_ao);  cudaGetSymbolAddress((void**)&xo, g_xo);
    cudaGetSymbolAddress((void**)&xn2,g_xn2); cudaGetSymbolAddress((void**)&hb, g_hb);
    cudaGetSymbolAddress((void**)&wq, g_wq);  cudaGetSymbolAddress((void**)&wkv,g_wkv);
    cudaGetSymbolAddress((void**)&wp, g_wp);  cudaGetSymbolAddress((void**)&wf1,g_wf1);
    cudaGetSymbolAddress((void**)&wf2,g_wf2);

    cudaFuncSetAttribute(gemm_mma<0,1>, cudaFuncAttributeMaxDynamicSharedMemorySize, GEMM_SMEM_BYTES);
    cudaFuncSetAttribute(gemm_mma<1,1>, cudaFuncAttributeMaxDynamicSharedMemorySize, GEMM_SMEM_BYTES);
    cudaFuncSetAttribute(gemm_mma<2,0>, cudaFuncAttributeMaxDynamicSharedMemorySize, GEMM_SMEM_BYTES);
    cudaFuncSetAttribute(gemm_mma<3,0>, cudaFuncAttributeMaxDynamicSharedMemorySize, GEMM_SMEM_BYTES);
    cudaFuncSetAttribute(attn_kernel,   cudaFuncAttributeMaxDynamicSharedMemorySize, ATTN_SMEM_BYTES);

    wt_transpose_all<<<(442368+255)/256,256>>>(q_w, kv_w, proj_w, fc1_w, fc2_w,
                                               wq, wkv, wp, wf1, wf2);

    ln1_gather_kernel<<<MROWS, CDIM>>>(x, x1, n1g, n1b, xw, x1w);

    gemm_mma<0,1><<<dim3(MROWS/128, CDIM/64),  256, GEMM_SMEM_BYTES>>>(x1w, wq,  q_b,  nullptr, qb,  MROWS, CDIM,   CDIM);
    gemm_mma<0,1><<<dim3(MROWS/128, 2*CDIM/64),256, GEMM_SMEM_BYTES>>>(xw,  wkv, kv_b, nullptr, kvb, MROWS, 2*CDIM, CDIM);

    attn_kernel<<<2048, 384, ATTN_SMEM_BYTES>>>(qb, kvb, rpb, mask, ao);

    gemm_mma<2,0><<<dim3(MROWS/128, CDIM/64),  256, GEMM_SMEM_BYTES>>>(ao,  wp,  proj_b, x,  xo, MROWS, CDIM, CDIM);

    ln2_kernel<<<MROWS, CDIM>>>(xo, n2g, n2b, xn2);

    gemm_mma<1,1><<<dim3(MROWS/128, HIDDEN/64),256, GEMM_SMEM_BYTES>>>(xn2, wf1, fc1_b, nullptr, hb, MROWS, HIDDEN, CDIM);
    gemm_mma<3,0><<<dim3(MROWS/128, CDIM/64),  256, GEMM_SMEM_BYTES>>>(hb,  wf2, fc2_b, xo, (float*)d_out, MROWS, CDIM, HIDDEN);
}

// round 12
// speedup vs baseline: 1.4630x; 1.4630x over previous
#include <cuda_runtime.h>
#include <cuda_bf16.h>
#include <cstdint>

#define HH 128
#define WW_ 256
#define CDIM 192
#define HDIM 32
#define HIDDEN 768
#define MROWS 131072
#define SHIFT 4

__device__ __nv_bfloat16 g_xw [(size_t)MROWS*CDIM];
__device__ __nv_bfloat16 g_x1w[(size_t)MROWS*CDIM];
__device__ __nv_bfloat16 g_qb [(size_t)MROWS*CDIM];
__device__ __nv_bfloat16 g_kvb[(size_t)MROWS*2*CDIM];
__device__ __nv_bfloat16 g_ao [(size_t)MROWS*CDIM];
__device__ float         g_xo [(size_t)MROWS*CDIM];
__device__ __nv_bfloat16 g_xn2[(size_t)MROWS*CDIM];
__device__ __nv_bfloat16 g_hb [(size_t)MROWS*HIDDEN];
__device__ __nv_bfloat16 g_wq [CDIM*CDIM];
__device__ __nv_bfloat16 g_wkv[2*CDIM*CDIM];
__device__ __nv_bfloat16 g_wp [CDIM*CDIM];
__device__ __nv_bfloat16 g_wf1[HIDDEN*CDIM];
__device__ __nv_bfloat16 g_wf2[CDIM*HIDDEN];

__device__ __forceinline__ uint32_t smem_u32(const void* p){
    uint32_t r; asm("{ .reg .u64 t; cvta.to.shared.u64 t, %1; cvt.u32.u64 %0, t; }":"=r"(r):"l"(p)); return r;
}
__device__ __forceinline__ int win_src_row(int r){
    int b_=r>>6, t=r&63, b=b_>>9, wid=b_&511;
    int h=(((wid>>5)<<3)+(t>>3)+SHIFT)&(HH-1);
    int w=(((wid&31)<<3)+(t&7)+SHIFT)&(WW_-1);
    return (b<<15)+(h<<8)+w;
}
__device__ __forceinline__ float warp_sum(float v){
#pragma unroll
    for(int o=16;o>0;o>>=1) v+=__shfl_xor_sync(0xffffffffu,v,o);
    return v;
}
__device__ __forceinline__ float gelu_exact(float v){ return 0.5f*v*(1.0f+erff(v*0.70710678118654752f)); }
__device__ __forceinline__ uint32_t bf2pack(float lo,float hi){
    uint32_t r; asm("cvt.rn.bf16x2.f32 %0, %1, %2;":"=r"(r):"f"(hi),"f"(lo)); return r;
}
__device__ __forceinline__ void cp_async16(uint32_t dst, const void* src){
    asm volatile("cp.async.cg.shared.global [%0], [%1], 16;"::"r"(dst),"l"(src):"memory");
}
__device__ __forceinline__ void cp_commit(){ asm volatile("cp.async.commit_group;":::"memory"); }
template<int N> __device__ __forceinline__ void cp_wait(){ asm volatile("cp.async.wait_group %0;"::"n"(N):"memory"); }

// ---------------------------------------------------------------------------
// Fused weight prep: all five [K,N]->[N,K] bf16 transposes in ONE launch.
// ---------------------------------------------------------------------------
__global__ void wt_transpose_all(const float* __restrict__ q_w, const float* __restrict__ kv_w,
                                 const float* __restrict__ proj_w, const float* __restrict__ fc1_w,
                                 const float* __restrict__ fc2_w,
                                 __nv_bfloat16* __restrict__ wq, __nv_bfloat16* __restrict__ wkv,
                                 __nv_bfloat16* __restrict__ wp, __nv_bfloat16* __restrict__ wf1,
                                 __nv_bfloat16* __restrict__ wf2){
    int i = blockIdx.x*256+threadIdx.x;
    const float* s; __nv_bfloat16* d; int K, N;
    if      (i < 36864)  { s=q_w;    d=wq;  K=CDIM;   N=CDIM;   }
    else if (i < 110592) { s=kv_w;   d=wkv; K=CDIM;   N=2*CDIM; i-=36864;  }
    else if (i < 147456) { s=proj_w; d=wp;  K=CDIM;   N=CDIM;   i-=110592; }
    else if (i < 294912) { s=fc1_w;  d=wf1; K=CDIM;   N=HIDDEN; i-=147456; }
    else if (i < 442368) { s=fc2_w;  d=wf2; K=HIDDEN; N=CDIM;   i-=294912; }
    else return;
    int n=i/K, k=i-n*K;
    d[i] = __float2bfloat16(s[(size_t)k*N+n]);
}

__global__ void ln1_gather_kernel(const float* __restrict__ x, const float* __restrict__ x1,
                                  const float* __restrict__ g, const float* __restrict__ bb,
                                  __nv_bfloat16* __restrict__ xw, __nv_bfloat16* __restrict__ x1w){
    int r=blockIdx.x, src=win_src_row(r), t=threadIdx.x;
    float v0=x[(size_t)src*CDIM+t], v1=x1[(size_t)src*CDIM+t];
    float s0=warp_sum(v0), q0=warp_sum(v0*v0), s1=warp_sum(v1), q1=warp_sum(v1*v1);
    __shared__ float red[4][6];
    int wp=t>>5, ln=t&31;
    if(ln==0){ red[0][wp]=s0; red[1][wp]=q0; red[2][wp]=s1; red[3][wp]=q1; }
    __syncthreads();
    float S0=0,Q0=0,S1=0,Q1=0;
#pragma unroll
    for(int i=0;i<6;i++){ S0+=red[0][i]; Q0+=red[1][i]; S1+=red[2][i]; Q1+=red[3][i]; }
    const float inv=1.0f/CDIM;
    float m0=S0*inv, m1=S1*inv;
    float r0=rsqrtf(Q0*inv-m0*m0+1e-5f), r1=rsqrtf(Q1*inv-m1*m1+1e-5f);
    float gg=g[t], bv=bb[t];
    xw [(size_t)r*CDIM+t]=__float2bfloat16((v0-m0)*r0*gg+bv);
    x1w[(size_t)r*CDIM+t]=__float2bfloat16((v1-m1)*r1*gg+bv);
}

__global__ void ln2_kernel(const float* __restrict__ x, const float* __restrict__ g,
                           const float* __restrict__ bb, __nv_bfloat16* __restrict__ out){
    int r=blockIdx.x, t=threadIdx.x;
    float v=x[(size_t)r*CDIM+t];
    float s=warp_sum(v), q=warp_sum(v*v);
    __shared__ float red[2][6];
    int wp=t>>5, ln=t&31;
    if(ln==0){ red[0][wp]=s; red[1][wp]=q; }
    __syncthreads();
    float S=0,Q=0;
#pragma unroll
    for(int i=0;i<6;i++){ S+=red[0][i]; Q+=red[1][i]; }
    const float inv=1.0f/CDIM;
    float m=S*inv, rs=rsqrtf(Q*inv-m*m+1e-5f);
    out[(size_t)r*CDIM+t]=__float2bfloat16((v-m)*rs*g[t]+bb[t]);
}

// ---------------------------------------------------------------------------
// HMMA bf16 GEMM: C[M,N] = A[M,K] @ Bw[N,K]^T.  BM=128 BN=64 BK=64, 256 thr,
// 8 warps (4 M x 2 N), warp tile 32x32, mma.m16n8k16, cp.async double buffer.
// R9 inner loop (measured best) + minBlocksPerMultiprocessor=3 to lift the
// smem/L1-bandwidth utilization (R9: L1=64%, occ=23% @ 2 CTAs/SM).
// EPI: 0 bias, 1 bias+gelu, 2 bias+scatter+residual, 3 bias+residual.
// ---------------------------------------------------------------------------
#define GEMM_SMEM_BYTES (49152 + 1024)
#define ABUF 16384
#define BUFB 24576

template <int EPI, int OUTBF>
__global__ __launch_bounds__(256, 3)
void gemm_mma(const __nv_bfloat16* __restrict__ A, const __nv_bfloat16* __restrict__ Bw,
              const float* __restrict__ bias, const float* __restrict__ res,
              void* __restrict__ Cv, int M, int N, int K){
    extern __shared__ char dsm[];
    uint32_t base = (smem_u32(dsm)+1023u)&~1023u;

    int tid=threadIdx.x, lane=tid&31, wid=tid>>5;
    int wm=wid&3, wn=wid>>2;
    int m0=blockIdx.x*128, n0=blockIdx.y*64;

    float acc[2][4][4];
#pragma unroll
    for(int a=0;a<2;a++)
#pragma unroll
        for(int b=0;b<4;b++)
#pragma unroll
            for(int c=0;c<4;c++) acc[a][b][c]=0.0f;

    auto stage=[&](int buf,int k0){
        uint32_t sA=base+buf*BUFB, sB=sA+ABUF;
#pragma unroll
        for(int l=0;l<4;l++){           // A: 1024 x 16B
            int i=tid+l*256, rr=i>>3, cc=i&7;
            uint32_t off=rr*128+cc*16;
            cp_async16(sA+(off^((off>>3)&0x70)), A+(size_t)(m0+rr)*K+k0+cc*8);
        }
#pragma unroll
        for(int l=0;l<2;l++){           // B: 512 x 16B
            int i=tid+l*256, rr=i>>3, cc=i&7;
            uint32_t off=rr*128+cc*16;
            cp_async16(sB+(off^((off>>3)&0x70)), Bw+(size_t)(n0+rr)*K+k0+cc*8);
        }
        cp_commit();
    };

    int nch=K>>6;
    stage(0,0);
    for(int c=0;c<nch;c++){
        if(c+1<nch){ stage((c+1)&1,(c+1)<<6); cp_wait<1>(); }
        else cp_wait<0>();
        __syncthreads();

        uint32_t sA=base+(c&1)*BUFB, sB=sA+ABUF;
#pragma unroll
        for(int kk=0;kk<4;kk++){
            uint32_t af[2][4];
#pragma unroll
            for(int mt=0;mt<2;mt++){
                int row=wm*32+mt*16+(lane&15);
                uint32_t off=row*128+kk*32+(lane>>4)*16;
                off^=((off>>3)&0x70);
                asm volatile("ldmatrix.sync.aligned.m8n8.x4.shared.b16 {%0,%1,%2,%3}, [%4];"
                    :"=r"(af[mt][0]),"=r"(af[mt][1]),"=r"(af[mt][2]),"=r"(af[mt][3]):"r"(sA+off));
            }
            uint32_t bf[4][2];
#pragma unroll
            for(int nt=0;nt<4;nt++){
                int rowb=wn*32+nt*8+(lane&7);
                uint32_t off=rowb*128+kk*32+((lane>>3)&1)*16;
                off^=((off>>3)&0x70);
                asm volatile("ldmatrix.sync.aligned.m8n8.x2.shared.b16 {%0,%1}, [%2];"
                    :"=r"(bf[nt][0]),"=r"(bf[nt][1]):"r"(sB+off));
            }
#pragma unroll
            for(int mt=0;mt<2;mt++)
#pragma unroll
                for(int nt=0;nt<4;nt++)
                    asm volatile("mma.sync.aligned.m16n8k16.row.col.f32.bf16.bf16.f32 "
                        "{%0,%1,%2,%3}, {%4,%5,%6,%7}, {%8,%9}, {%0,%1,%2,%3};"
                        :"+f"(acc[mt][nt][0]),"+f"(acc[mt][nt][1]),"+f"(acc[mt][nt][2]),"+f"(acc[mt][nt][3])
                        :"r"(af[mt][0]),"r"(af[mt][1]),"r"(af[mt][2]),"r"(af[mt][3]),
                         "r"(bf[nt][0]),"r"(bf[nt][1]));
        }
        __syncthreads();
    }

#pragma unroll
    for(int mt=0;mt<2;mt++){
#pragma unroll
        for(int half=0;half<2;half++){
            int row=m0+wm*32+mt*16+(lane>>2)+half*8;
            int orow=(EPI==2)?win_src_row(row):row;
#pragma unroll
            for(int nt=0;nt<4;nt++){
                int col=n0+wn*32+nt*8+(lane&3)*2;
                float v0=acc[mt][nt][half*2+0]+__ldg(bias+col);
                float v1=acc[mt][nt][half*2+1]+__ldg(bias+col+1);
                if(EPI==1){ v0=gelu_exact(v0); v1=gelu_exact(v1); }
                if(EPI==2||EPI==3){
                    const float* rp=res+(size_t)orow*N+col;
                    v0+=rp[0]; v1+=rp[1];
                }
                if(OUTBF){
                    *(uint32_t*)((__nv_bfloat16*)Cv+(size_t)orow*N+col)=bf2pack(v0,v1);
                }else{
                    *(float2*)((float*)Cv+(size_t)orow*N+col)=make_float2(v0,v1);
                }
            }
        }
    }
}

// ---------------------------------------------------------------------------
// Attention: one block per window, 384 thr (6 heads x 64 rows), f32x2 FMA,
// single-pass softmax (scores tiny; mask -100 underflows exp -> 0).
// ---------------------------------------------------------------------------
#define ATTN_SMEM_BYTES 112256

__global__ __launch_bounds__(384)
void attn_kernel(const __nv_bfloat16* __restrict__ q, const __nv_bfloat16* __restrict__ kv,
                 const float* __restrict__ rpb, const float* __restrict__ mask,
                 __nv_bfloat16* __restrict__ ao){
    extern __shared__ char dsm[];
    unsigned long long* K8=(unsigned long long*)dsm;   // [64][96] f32x2
    unsigned long long* V8=K8+64*96;
    __nv_bfloat16* Ms=(__nv_bfloat16*)(V8+64*96);      // [64][66]
    float* Rp=(float*)(Ms+64*66);                      // [1350]

    int win=blockIdx.x, tid=threadIdx.x;
    const __nv_bfloat162* kvb=(const __nv_bfloat162*)(kv+(size_t)win*64*384);
    for(int i=tid;i<64*192;i+=384){
        int row=i/192, p=i-row*192;
        float2 f=__bfloat1622float2(kvb[row*192+p]);
        unsigned long long pk;
        asm("mov.b64 %0,{%1,%2};":"=l"(pk):"r"(__float_as_uint(f.x)),"r"(__float_as_uint(f.y)));
        if(p<96) K8[row*96+p]=pk; else V8[row*96+p-96]=pk;
    }
    const float* mg=mask+(size_t)(win&511)*4096;
    for(int i=tid;i<4096;i+=384) Ms[(i>>6)*66+(i&63)]=__float2bfloat16(mg[i]);
    for(int i=tid;i<1350;i+=384) Rp[i]=rpb[i];

    int h=tid/64, t=tid-h*64;
    unsigned long long q2[16];
    {
        const __nv_bfloat162* qp=(const __nv_bfloat162*)(q+((size_t)win*64+t)*CDIM+h*HDIM);
        const float sc=0.17677669529663688f;
#pragma unroll
        for(int d=0;d<16;d++){
            float2 f=__bfloat1622float2(qp[d]);
            f.x*=sc; f.y*=sc;
            asm("mov.b64 %0,{%1,%2};":"=l"(q2[d]):"r"(__float_as_uint(f.x)),"r"(__float_as_uint(f.y)));
        }
    }
    __syncthreads();

    int i1=t>>3, j1=t&7, kb=h*16;
    unsigned long long od[16];
#pragma unroll
    for(int d=0;d<16;d++) od[d]=0ULL;
    float sum=0.0f;

    for(int m=0;m<64;m++){
        const unsigned long long* kp=K8+m*96+kb;
        unsigned long long a0=0,a1=0,a2=0,a3=0;
#pragma unroll
        for(int d=0;d<16;d+=4){
            asm("fma.rn.f32x2 %0, %1, %2, %0;":"+l"(a0):"l"(q2[d+0]),"l"(kp[d+0]));
            asm("fma.rn.f32x2 %0, %1, %2, %0;":"+l"(a1):"l"(q2[d+1]),"l"(kp[d+1]));
            asm("fma.rn.f32x2 %0, %1, %2, %0;":"+l"(a2):"l"(q2[d+2]),"l"(kp[d+2]));
            asm("fma.rn.f32x2 %0, %1, %2, %0;":"+l"(a3):"l"(q2[d+3]),"l"(kp[d+3]));
        }
        uint32_t lo,hi; float s;
        asm("mov.b64 {%0,%1}, %2;":"=r"(lo),"=r"(hi):"l"(a0)); s =__uint_as_float(lo)+__uint_as_float(hi);
        asm("mov.b64 {%0,%1}, %2;":"=r"(lo),"=r"(hi):"l"(a1)); s+=__uint_as_float(lo)+__uint_as_float(hi);
        asm("mov.b64 {%0,%1}, %2;":"=r"(lo),"=r"(hi):"l"(a2)); s+=__uint_as_float(lo)+__uint_as_float(hi);
        asm("mov.b64 {%0,%1}, %2;":"=r"(lo),"=r"(hi):"l"(a3)); s+=__uint_as_float(lo)+__uint_as_float(hi);

        int ridx=(i1-(m>>3)+7)*15+(j1-(m&7)+7);
        s += Rp[ridx*6+h] + __bfloat162float(Ms[t*66+m]);
        float e=__expf(s);
        sum+=e;
        unsigned long long e2;
        asm("mov.b64 %0,{%1,%1};":"=l"(e2):"r"(__float_as_uint(e)));
        const unsigned long long* vp=V8+m*96+kb;
#pragma unroll
        for(int d=0;d<16;d++)
            asm("fma.rn.f32x2 %0, %1, %2, %0;":"+l"(od[d]):"l"(e2),"l"(vp[d]));
    }
    float inv=1.0f/sum;
    __nv_bfloat162* orow=(__nv_bfloat162*)(ao+((size_t)win*64+t)*CDIM+h*HDIM);
#pragma unroll
    for(int d=0;d<16;d++){
        uint32_t lo,hi;
        asm("mov.b64 {%0,%1}, %2;":"=r"(lo),"=r"(hi):"l"(od[d]));
        orow[d]=__floats2bfloat162_rn(__uint_as_float(lo)*inv,__uint_as_float(hi)*inv);
    }
}

extern "C" void kernel_launch(void* const* d_in, const int* in_sizes, int n_in,
                              void* d_out, int out_size){
    const float* x     =(const float*)d_in[0];
    const float* x1    =(const float*)d_in[1];
    const float* mask  =(const float*)d_in[2];
    const float* n1g   =(const float*)d_in[3];
    const float* n1b   =(const float*)d_in[4];
    const float* q_w   =(const float*)d_in[5];
    const float* q_b   =(const float*)d_in[6];
    const float* kv_w  =(const float*)d_in[7];
    const float* kv_b  =(const float*)d_in[8];
    const float* rpb   =(const float*)d_in[9];
    const float* proj_w=(const float*)d_in[10];
    const float* proj_b=(const float*)d_in[11];
    const float* n2g   =(const float*)d_in[12];
    const float* n2b   =(const float*)d_in[13];
    const float* fc1_w =(const float*)d_in[14];
    const float* fc1_b =(const float*)d_in[15];
    const float* fc2_w =(const float*)d_in[16];
    const float* fc2_b =(const float*)d_in[17];

    __nv_bfloat16 *xw,*x1w,*qb,*kvb,*ao,*xn2,*hb,*wq,*wkv,*wp,*wf1,*wf2;
    float* xo;
    cudaGetSymbolAddress((void**)&xw, g_xw);  cudaGetSymbolAddress((void**)&x1w,g_x1w);
    cudaGetSymbolAddress((void**)&qb, g_qb);  cudaGetSymbolAddress((void**)&kvb,g_kvb);
    cudaGetSymbolAddress((void**)&ao, g_ao);  cudaGetSymbolAddress((void**)&xo, g_xo);
    cudaGetSymbolAddress((void**)&xn2,g_xn2); cudaGetSymbolAddress((void**)&hb, g_hb);
    cudaGetSymbolAddress((void**)&wq, g_wq);  cudaGetSymbolAddress((void**)&wkv,g_wkv);
    cudaGetSymbolAddress((void**)&wp, g_wp);  cudaGetSymbolAddress((void**)&wf1,g_wf1);
    cudaGetSymbolAddress((void**)&wf2,g_wf2);

    cudaFuncSetAttribute(gemm_mma<0,1>, cudaFuncAttributeMaxDynamicSharedMemorySize, GEMM_SMEM_BYTES);
    cudaFuncSetAttribute(gemm_mma<1,1>, cudaFuncAttributeMaxDynamicSharedMemorySize, GEMM_SMEM_BYTES);
    cudaFuncSetAttribute(gemm_mma<2,0>, cudaFuncAttributeMaxDynamicSharedMemorySize, GEMM_SMEM_BYTES);
    cudaFuncSetAttribute(gemm_mma<3,0>, cudaFuncAttributeMaxDynamicSharedMemorySize, GEMM_SMEM_BYTES);
    cudaFuncSetAttribute(attn_kernel,   cudaFuncAttributeMaxDynamicSharedMemorySize, ATTN_SMEM_BYTES);

    wt_transpose_all<<<(442368+255)/256,256>>>(q_w, kv_w, proj_w, fc1_w, fc2_w,
                                               wq, wkv, wp, wf1, wf2);

    ln1_gather_kernel<<<MROWS, CDIM>>>(x, x1, n1g, n1b, xw, x1w);

    gemm_mma<0,1><<<dim3(MROWS/128, CDIM/64),  256, GEMM_SMEM_BYTES>>>(x1w, wq,  q_b,  nullptr, qb,  MROWS, CDIM,   CDIM);
    gemm_mma<0,1><<<dim3(MROWS/128, 2*CDIM/64),256, GEMM_SMEM_BYTES>>>(xw,  wkv, kv_b, nullptr, kvb, MROWS, 2*CDIM, CDIM);

    attn_kernel<<<2048, 384, ATTN_SMEM_BYTES>>>(qb, kvb, rpb, mask, ao);

    gemm_mma<2,0><<<dim3(MROWS/128, CDIM/64),  256, GEMM_SMEM_BYTES>>>(ao,  wp,  proj_b, x,  xo, MROWS, CDIM, CDIM);

    ln2_kernel<<<MROWS, CDIM>>>(xo, n2g, n2b, xn2);

    gemm_mma<1,1><<<dim3(MROWS/128, HIDDEN/64),256, GEMM_SMEM_BYTES>>>(xn2, wf1, fc1_b, nullptr, hb, MROWS, HIDDEN, CDIM);
    gemm_mma<3,0><<<dim3(MROWS/128, CDIM/64),  256, GEMM_SMEM_BYTES>>>(hb,  wf2, fc2_b, xo, (float*)d_out, MROWS, CDIM, HIDDEN);
}

// round 13
// speedup vs baseline: 1.4846x; 1.0148x over previous
#include <cuda_runtime.h>
#include <cuda_bf16.h>
#include <cstdint>

#define HH 128
#define WW_ 256
#define CDIM 192
#define HDIM 32
#define HIDDEN 768
#define MROWS 131072
#define SHIFT 4
#define PGRID 304

__device__ __nv_bfloat16 g_xw [(size_t)MROWS*CDIM];
__device__ __nv_bfloat16 g_x1w[(size_t)MROWS*CDIM];
__device__ __nv_bfloat16 g_qb [(size_t)MROWS*CDIM];
__device__ __nv_bfloat16 g_kvb[(size_t)MROWS*2*CDIM];
__device__ __nv_bfloat16 g_ao [(size_t)MROWS*CDIM];
__device__ float         g_xo [(size_t)MROWS*CDIM];
__device__ __nv_bfloat16 g_xn2[(size_t)MROWS*CDIM];
__device__ __nv_bfloat16 g_hb [(size_t)MROWS*HIDDEN];
__device__ __nv_bfloat16 g_wq [CDIM*CDIM];
__device__ __nv_bfloat16 g_wkv[2*CDIM*CDIM];
__device__ __nv_bfloat16 g_wp [CDIM*CDIM];
__device__ __nv_bfloat16 g_wf1[HIDDEN*CDIM];
__device__ __nv_bfloat16 g_wf2[CDIM*HIDDEN];

__device__ __forceinline__ uint32_t smem_u32(const void* p){
    uint32_t r; asm("{ .reg .u64 t; cvta.to.shared.u64 t, %1; cvt.u32.u64 %0, t; }":"=r"(r):"l"(p)); return r;
}
__device__ __forceinline__ int win_src_row(int r){
    int b_=r>>6, t=r&63, b=b_>>9, wid=b_&511;
    int h=(((wid>>5)<<3)+(t>>3)+SHIFT)&(HH-1);
    int w=(((wid&31)<<3)+(t&7)+SHIFT)&(WW_-1);
    return (b<<15)+(h<<8)+w;
}
__device__ __forceinline__ float warp_sum(float v){
#pragma unroll
    for(int o=16;o>0;o>>=1) v+=__shfl_xor_sync(0xffffffffu,v,o);
    return v;
}
__device__ __forceinline__ float gelu_exact(float v){ return 0.5f*v*(1.0f+erff(v*0.70710678118654752f)); }
__device__ __forceinline__ uint32_t bf2pack(float lo,float hi){
    uint32_t r; asm("cvt.rn.bf16x2.f32 %0, %1, %2;":"=r"(r):"f"(hi),"f"(lo)); return r;
}
__device__ __forceinline__ void cp_async16(uint32_t dst, const void* src){
    asm volatile("cp.async.cg.shared.global [%0], [%1], 16;"::"r"(dst),"l"(src):"memory");
}
__device__ __forceinline__ void cp_commit(){ asm volatile("cp.async.commit_group;":::"memory"); }
template<int N> __device__ __forceinline__ void cp_wait(){ asm volatile("cp.async.wait_group %0;"::"n"(N):"memory"); }

// ---------------------------------------------------------------------------
// Fused weight prep: all five [K,N]->[N,K] bf16 transposes in ONE launch.
// ---------------------------------------------------------------------------
__global__ void wt_transpose_all(const float* __restrict__ q_w, const float* __restrict__ kv_w,
                                 const float* __restrict__ proj_w, const float* __restrict__ fc1_w,
                                 const float* __restrict__ fc2_w,
                                 __nv_bfloat16* __restrict__ wq, __nv_bfloat16* __restrict__ wkv,
                                 __nv_bfloat16* __restrict__ wp, __nv_bfloat16* __restrict__ wf1,
                                 __nv_bfloat16* __restrict__ wf2){
    int i = blockIdx.x*256+threadIdx.x;
    const float* s; __nv_bfloat16* d; int K, N;
    if      (i < 36864)  { s=q_w;    d=wq;  K=CDIM;   N=CDIM;   }
    else if (i < 110592) { s=kv_w;   d=wkv; K=CDIM;   N=2*CDIM; i-=36864;  }
    else if (i < 147456) { s=proj_w; d=wp;  K=CDIM;   N=CDIM;   i-=110592; }
    else if (i < 294912) { s=fc1_w;  d=wf1; K=CDIM;   N=HIDDEN; i-=147456; }
    else if (i < 442368) { s=fc2_w;  d=wf2; K=HIDDEN; N=CDIM;   i-=294912; }
    else return;
    int n=i/K, k=i-n*K;
    d[i] = __float2bfloat16(s[(size_t)k*N+n]);
}

__global__ void ln1_gather_kernel(const float* __restrict__ x, const float* __restrict__ x1,
                                  const float* __restrict__ g, const float* __restrict__ bb,
                                  __nv_bfloat16* __restrict__ xw, __nv_bfloat16* __restrict__ x1w){
    int r=blockIdx.x, src=win_src_row(r), t=threadIdx.x;
    float v0=x[(size_t)src*CDIM+t], v1=x1[(size_t)src*CDIM+t];
    float s0=warp_sum(v0), q0=warp_sum(v0*v0), s1=warp_sum(v1), q1=warp_sum(v1*v1);
    __shared__ float red[4][6];
    int wp=t>>5, ln=t&31;
    if(ln==0){ red[0][wp]=s0; red[1][wp]=q0; red[2][wp]=s1; red[3][wp]=q1; }
    __syncthreads();
    float S0=0,Q0=0,S1=0,Q1=0;
#pragma unroll
    for(int i=0;i<6;i++){ S0+=red[0][i]; Q0+=red[1][i]; S1+=red[2][i]; Q1+=red[3][i]; }
    const float inv=1.0f/CDIM;
    float m0=S0*inv, m1=S1*inv;
    float r0=rsqrtf(Q0*inv-m0*m0+1e-5f), r1=rsqrtf(Q1*inv-m1*m1+1e-5f);
    float gg=g[t], bv=bb[t];
    xw [(size_t)r*CDIM+t]=__float2bfloat16((v0-m0)*r0*gg+bv);
    x1w[(size_t)r*CDIM+t]=__float2bfloat16((v1-m1)*r1*gg+bv);
}

__global__ void ln2_kernel(const float* __restrict__ x, const float* __restrict__ g,
                           const float* __restrict__ bb, __nv_bfloat16* __restrict__ out){
    int r=blockIdx.x, t=threadIdx.x;
    float v=x[(size_t)r*CDIM+t];
    float s=warp_sum(v), q=warp_sum(v*v);
    __shared__ float red[2][6];
    int wp=t>>5, ln=t&31;
    if(ln==0){ red[0][wp]=s; red[1][wp]=q; }
    __syncthreads();
    float S=0,Q=0;
#pragma unroll
    for(int i=0;i<6;i++){ S+=red[0][i]; Q+=red[1][i]; }
    const float inv=1.0f/CDIM;
    float m=S*inv, rs=rsqrtf(Q*inv-m*m+1e-5f);
    out[(size_t)r*CDIM+t]=__float2bfloat16((v-m)*rs*g[t]+bb[t]);
}

// ---------------------------------------------------------------------------
// Persistent-streaming HMMA bf16 GEMM: C = A @ Bw^T.  BM=128 BN=64 BK=64,
// 256 thr, 8 warps (4x2), warp tile 32x32 (R9 inner loop, measured best).
// Fixed grid of PGRID CTAs; each streams many tiles with the cp.async
// pipeline continuing ACROSS tile boundaries (no per-tile prologue drain).
// EPI: 0 bias, 1 bias+gelu, 2 bias+scatter+residual, 3 bias+residual.
// ---------------------------------------------------------------------------
#define GEMM_SMEM_BYTES (49152 + 1024)
#define ABUF 16384
#define BUFB 24576

template <int EPI, int OUTBF>
__global__ __launch_bounds__(256)
void gemm_mma(const __nv_bfloat16* __restrict__ A, const __nv_bfloat16* __restrict__ Bw,
              const float* __restrict__ bias, const float* __restrict__ res,
              void* __restrict__ Cv, int M, int N, int K){
    extern __shared__ char dsm[];
    uint32_t base = (smem_u32(dsm)+1023u)&~1023u;

    int tid=threadIdx.x, lane=tid&31, wid=tid>>5;
    int wm=wid&3, wn=wid>>2;
    int Nb=N>>6, nch=K>>6;
    int ntiles=(M>>7)*Nb;

    auto stage=[&](int buf,int m0,int n0,int k0){
        uint32_t sA=base+buf*BUFB, sB=sA+ABUF;
#pragma unroll
        for(int l=0;l<4;l++){           // A: 1024 x 16B
            int i=tid+l*256, rr=i>>3, cc=i&7;
            uint32_t off=rr*128+cc*16;
            cp_async16(sA+(off^((off>>3)&0x70)), A+(size_t)(m0+rr)*K+k0+cc*8);
        }
#pragma unroll
        for(int l=0;l<2;l++){           // B: 512 x 16B
            int i=tid+l*256, rr=i>>3, cc=i&7;
            uint32_t off=rr*128+cc*16;
            cp_async16(sB+(off^((off>>3)&0x70)), Bw+(size_t)(n0+rr)*K+k0+cc*8);
        }
        cp_commit();
    };

    int t0=blockIdx.x;
    if(t0>=ntiles) return;
    {
        int m=t0/Nb, n=t0-m*Nb;
        stage(0, m<<7, n<<6, 0);        // pipeline fill: once per CTA
    }
    int gbuf=0;

    for(int t=t0; t<ntiles; t+=PGRID){
        int m=t/Nb, n=t-m*Nb;
        int m0=m<<7, n0=n<<6;

        float acc[2][4][4];
#pragma unroll
        for(int a=0;a<2;a++)
#pragma unroll
            for(int b=0;b<4;b++)
#pragma unroll
                for(int c=0;c<4;c++) acc[a][b][c]=0.0f;

        for(int c=0;c<nch;c++){
            int nt=t, nc=c+1;
            if(nc==nch){ nt=t+PGRID; nc=0; }
            if(nt<ntiles){
                int mm=nt/Nb, nn=nt-mm*Nb;
                stage(gbuf^1, mm<<7, nn<<6, nc<<6);
            } else cp_commit();          // keep group count uniform
            cp_wait<1>();
            __syncthreads();

            uint32_t sA=base+gbuf*BUFB, sB=sA+ABUF;
#pragma unroll
            for(int kk=0;kk<4;kk++){
                uint32_t af[2][4];
#pragma unroll
                for(int mt=0;mt<2;mt++){
                    int row=wm*32+mt*16+(lane&15);
                    uint32_t off=row*128+kk*32+(lane>>4)*16;
                    off^=((off>>3)&0x70);
                    asm volatile("ldmatrix.sync.aligned.m8n8.x4.shared.b16 {%0,%1,%2,%3}, [%4];"
                        :"=r"(af[mt][0]),"=r"(af[mt][1]),"=r"(af[mt][2]),"=r"(af[mt][3]):"r"(sA+off));
                }
                uint32_t bf[4][2];
#pragma unroll
                for(int nt2=0;nt2<4;nt2++){
                    int rowb=wn*32+nt2*8+(lane&7);
                    uint32_t off=rowb*128+kk*32+((lane>>3)&1)*16;
                    off^=((off>>3)&0x70);
                    asm volatile("ldmatrix.sync.aligned.m8n8.x2.shared.b16 {%0,%1}, [%2];"
                        :"=r"(bf[nt2][0]),"=r"(bf[nt2][1]):"r"(sB+off));
                }
#pragma unroll
                for(int mt=0;mt<2;mt++)
#pragma unroll
                    for(int nt2=0;nt2<4;nt2++)
                        asm volatile("mma.sync.aligned.m16n8k16.row.col.f32.bf16.bf16.f32 "
                            "{%0,%1,%2,%3}, {%4,%5,%6,%7}, {%8,%9}, {%0,%1,%2,%3};"
                            :"+f"(acc[mt][nt2][0]),"+f"(acc[mt][nt2][1]),"+f"(acc[mt][nt2][2]),"+f"(acc[mt][nt2][3])
                            :"r"(af[mt][0]),"r"(af[mt][1]),"r"(af[mt][2]),"r"(af[mt][3]),
                             "r"(bf[nt2][0]),"r"(bf[nt2][1]));
            }
            __syncthreads();
            gbuf^=1;
        }

        // epilogue (overlaps next tile's in-flight chunk-0 loads)
#pragma unroll
        for(int mt=0;mt<2;mt++){
#pragma unroll
            for(int half=0;half<2;half++){
                int row=m0+wm*32+mt*16+(lane>>2)+half*8;
                int orow=(EPI==2)?win_src_row(row):row;
#pragma unroll
                for(int nt2=0;nt2<4;nt2++){
                    int col=n0+wn*32+nt2*8+(lane&3)*2;
                    float v0=acc[mt][nt2][half*2+0]+__ldg(bias+col);
                    float v1=acc[mt][nt2][half*2+1]+__ldg(bias+col+1);
                    if(EPI==1){ v0=gelu_exact(v0); v1=gelu_exact(v1); }
                    if(EPI==2||EPI==3){
                        const float* rp=res+(size_t)orow*N+col;
                        v0+=rp[0]; v1+=rp[1];
                    }
                    if(OUTBF){
                        *(uint32_t*)((__nv_bfloat16*)Cv+(size_t)orow*N+col)=bf2pack(v0,v1);
                    }else{
                        *(float2*)((float*)Cv+(size_t)orow*N+col)=make_float2(v0,v1);
                    }
                }
            }
        }
    }
}

// ---------------------------------------------------------------------------
// Attention: one block per window, 384 thr (6 heads x 64 rows), f32x2 FMA,
// single-pass softmax (scores tiny; mask -100 underflows exp -> 0).
// ---------------------------------------------------------------------------
#define ATTN_SMEM_BYTES 112256

__global__ __launch_bounds__(384)
void attn_kernel(const __nv_bfloat16* __restrict__ q, const __nv_bfloat16* __restrict__ kv,
                 const float* __restrict__ rpb, const float* __restrict__ mask,
                 __nv_bfloat16* __restrict__ ao){
    extern __shared__ char dsm[];
    unsigned long long* K8=(unsigned long long*)dsm;   // [64][96] f32x2
    unsigned long long* V8=K8+64*96;
    __nv_bfloat16* Ms=(__nv_bfloat16*)(V8+64*96);      // [64][66]
    float* Rp=(float*)(Ms+64*66);                      // [1350]

    int win=blockIdx.x, tid=threadIdx.x;
    const __nv_bfloat162* kvb=(const __nv_bfloat162*)(kv+(size_t)win*64*384);
    for(int i=tid;i<64*192;i+=384){
        int row=i/192, p=i-row*192;
        float2 f=__bfloat1622float2(kvb[row*192+p]);
        unsigned long long pk;
        asm("mov.b64 %0,{%1,%2};":"=l"(pk):"r"(__float_as_uint(f.x)),"r"(__float_as_uint(f.y)));
        if(p<96) K8[row*96+p]=pk; else V8[row*96+p-96]=pk;
    }
    const float* mg=mask+(size_t)(win&511)*4096;
    for(int i=tid;i<4096;i+=384) Ms[(i>>6)*66+(i&63)]=__float2bfloat16(mg[i]);
    for(int i=tid;i<1350;i+=384) Rp[i]=rpb[i];

    int h=tid/64, t=tid-h*64;
    unsigned long long q2[16];
    {
        const __nv_bfloat162* qp=(const __nv_bfloat162*)(q+((size_t)win*64+t)*CDIM+h*HDIM);
        const float sc=0.17677669529663688f;
#pragma unroll
        for(int d=0;d<16;d++){
            float2 f=__bfloat1622float2(qp[d]);
            f.x*=sc; f.y*=sc;
            asm("mov.b64 %0,{%1,%2};":"=l"(q2[d]):"r"(__float_as_uint(f.x)),"r"(__float_as_uint(f.y)));
        }
    }
    __syncthreads();

    int i1=t>>3, j1=t&7, kb=h*16;
    unsigned long long od[16];
#pragma unroll
    for(int d=0;d<16;d++) od[d]=0ULL;
    float sum=0.0f;

    for(int m=0;m<64;m++){
        const unsigned long long* kp=K8+m*96+kb;
        unsigned long long a0=0,a1=0,a2=0,a3=0;
#pragma unroll
        for(int d=0;d<16;d+=4){
            asm("fma.rn.f32x2 %0, %1, %2, %0;":"+l"(a0):"l"(q2[d+0]),"l"(kp[d+0]));
            asm("fma.rn.f32x2 %0, %1, %2, %0;":"+l"(a1):"l"(q2[d+1]),"l"(kp[d+1]));
            asm("fma.rn.f32x2 %0, %1, %2, %0;":"+l"(a2):"l"(q2[d+2]),"l"(kp[d+2]));
            asm("fma.rn.f32x2 %0, %1, %2, %0;":"+l"(a3):"l"(q2[d+3]),"l"(kp[d+3]));
        }
        uint32_t lo,hi; float s;
        asm("mov.b64 {%0,%1}, %2;":"=r"(lo),"=r"(hi):"l"(a0)); s =__uint_as_float(lo)+__uint_as_float(hi);
        asm("mov.b64 {%0,%1}, %2;":"=r"(lo),"=r"(hi):"l"(a1)); s+=__uint_as_float(lo)+__uint_as_float(hi);
        asm("mov.b64 {%0,%1}, %2;":"=r"(lo),"=r"(hi):"l"(a2)); s+=__uint_as_float(lo)+__uint_as_float(hi);
        asm("mov.b64 {%0,%1}, %2;":"=r"(lo),"=r"(hi):"l"(a3)); s+=__uint_as_float(lo)+__uint_as_float(hi);

        int ridx=(i1-(m>>3)+7)*15+(j1-(m&7)+7);
        s += Rp[ridx*6+h] + __bfloat162float(Ms[t*66+m]);
        float e=__expf(s);
        sum+=e;
        unsigned long long e2;
        asm("mov.b64 %0,{%1,%1};":"=l"(e2):"r"(__float_as_uint(e)));
        const unsigned long long* vp=V8+m*96+kb;
#pragma unroll
        for(int d=0;d<16;d++)
            asm("fma.rn.f32x2 %0, %1, %2, %0;":"+l"(od[d]):"l"(e2),"l"(vp[d]));
    }
    float inv=1.0f/sum;
    __nv_bfloat162* orow=(__nv_bfloat162*)(ao+((size_t)win*64+t)*CDIM+h*HDIM);
#pragma unroll
    for(int d=0;d<16;d++){
        uint32_t lo,hi;
        asm("mov.b64 {%0,%1}, %2;":"=r"(lo),"=r"(hi):"l"(od[d]));
        orow[d]=__floats2bfloat162_rn(__uint_as_float(lo)*inv,__uint_as_float(hi)*inv);
    }
}

extern "C" void kernel_launch(void* const* d_in, const int* in_sizes, int n_in,
                              void* d_out, int out_size){
    const float* x     =(const float*)d_in[0];
    const float* x1    =(const float*)d_in[1];
    const float* mask  =(const float*)d_in[2];
    const float* n1g   =(const float*)d_in[3];
    const float* n1b   =(const float*)d_in[4];
    const float* q_w   =(const float*)d_in[5];
    const float* q_b   =(const float*)d_in[6];
    const float* kv_w  =(const float*)d_in[7];
    const float* kv_b  =(const float*)d_in[8];
    const float* rpb   =(const float*)d_in[9];
    const float* proj_w=(const float*)d_in[10];
    const float* proj_b=(const float*)d_in[11];
    const float* n2g   =(const float*)d_in[12];
    const float* n2b   =(const float*)d_in[13];
    const float* fc1_w =(const float*)d_in[14];
    const float* fc1_b =(const float*)d_in[15];
    const float* fc2_w =(const float*)d_in[16];
    const float* fc2_b =(const float*)d_in[17];

    __nv_bfloat16 *xw,*x1w,*qb,*kvb,*ao,*xn2,*hb,*wq,*wkv,*wp,*wf1,*wf2;
    float* xo;
    cudaGetSymbolAddress((void**)&xw, g_xw);  cudaGetSymbolAddress((void**)&x1w,g_x1w);
    cudaGetSymbolAddress((void**)&qb, g_qb);  cudaGetSymbolAddress((void**)&kvb,g_kvb);
    cudaGetSymbolAddress((void**)&ao, g_ao);  cudaGetSymbolAddress((void**)&xo, g_xo);
    cudaGetSymbolAddress((void**)&xn2,g_xn2); cudaGetSymbolAddress((void**)&hb, g_hb);
    cudaGetSymbolAddress((void**)&wq, g_wq);  cudaGetSymbolAddress((void**)&wkv,g_wkv);
    cudaGetSymbolAddress((void**)&wp, g_wp);  cudaGetSymbolAddress((void**)&wf1,g_wf1);
    cudaGetSymbolAddress((void**)&wf2,g_wf2);

    cudaFuncSetAttribute(gemm_mma<0,1>, cudaFuncAttributeMaxDynamicSharedMemorySize, GEMM_SMEM_BYTES);
    cudaFuncSetAttribute(gemm_mma<1,1>, cudaFuncAttributeMaxDynamicSharedMemorySize, GEMM_SMEM_BYTES);
    cudaFuncSetAttribute(gemm_mma<2,0>, cudaFuncAttributeMaxDynamicSharedMemorySize, GEMM_SMEM_BYTES);
    cudaFuncSetAttribute(gemm_mma<3,0>, cudaFuncAttributeMaxDynamicSharedMemorySize, GEMM_SMEM_BYTES);
    cudaFuncSetAttribute(attn_kernel,   cudaFuncAttributeMaxDynamicSharedMemorySize, ATTN_SMEM_BYTES);

    wt_transpose_all<<<(442368+255)/256,256>>>(q_w, kv_w, proj_w, fc1_w, fc2_w,
                                               wq, wkv, wp, wf1, wf2);

    ln1_gather_kernel<<<MROWS, CDIM>>>(x, x1, n1g, n1b, xw, x1w);

    gemm_mma<0,1><<<PGRID, 256, GEMM_SMEM_BYTES>>>(x1w, wq,  q_b,  nullptr, qb,  MROWS, CDIM,   CDIM);
    gemm_mma<0,1><<<PGRID, 256, GEMM_SMEM_BYTES>>>(xw,  wkv, kv_b, nullptr, kvb, MROWS, 2*CDIM, CDIM);

    attn_kernel<<<2048, 384, ATTN_SMEM_BYTES>>>(qb, kvb, rpb, mask, ao);

    gemm_mma<2,0><<<PGRID, 256, GEMM_SMEM_BYTES>>>(ao,  wp,  proj_b, x,  xo, MROWS, CDIM, CDIM);

    ln2_kernel<<<MROWS, CDIM>>>(xo, n2g, n2b, xn2);

    gemm_mma<1,1><<<PGRID, 256, GEMM_SMEM_BYTES>>>(xn2, wf1, fc1_b, nullptr, hb, MROWS, HIDDEN, CDIM);
    gemm_mma<3,0><<<PGRID, 256, GEMM_SMEM_BYTES>>>(hb,  wf2, fc2_b, xo, (float*)d_out, MROWS, CDIM, HIDDEN);
}

// round 14
// speedup vs baseline: 1.5043x; 1.0133x over previous
#include <cuda_runtime.h>
#include <cuda_bf16.h>
#include <cstdint>

#define HH 128
#define WW_ 256
#define CDIM 192
#define HDIM 32
#define HIDDEN 768
#define MROWS 131072
#define SHIFT 4
#define PGRID 304

__device__ __nv_bfloat16 g_xw [(size_t)MROWS*CDIM];
__device__ __nv_bfloat16 g_x1w[(size_t)MROWS*CDIM];
__device__ __nv_bfloat16 g_qb [(size_t)MROWS*CDIM];
__device__ __nv_bfloat16 g_kvb[(size_t)MROWS*2*CDIM];
__device__ __nv_bfloat16 g_ao [(size_t)MROWS*CDIM];
__device__ float         g_xo [(size_t)MROWS*CDIM];
__device__ __nv_bfloat16 g_xn2[(size_t)MROWS*CDIM];
__device__ __nv_bfloat16 g_hb [(size_t)MROWS*HIDDEN];
__device__ __nv_bfloat16 g_wq [CDIM*CDIM];
__device__ __nv_bfloat16 g_wkv[2*CDIM*CDIM];
__device__ __nv_bfloat16 g_wp [CDIM*CDIM];
__device__ __nv_bfloat16 g_wf1[HIDDEN*CDIM];
__device__ __nv_bfloat16 g_wf2[CDIM*HIDDEN];

__device__ __forceinline__ uint32_t smem_u32(const void* p){
    uint32_t r; asm("{ .reg .u64 t; cvta.to.shared.u64 t, %1; cvt.u32.u64 %0, t; }":"=r"(r):"l"(p)); return r;
}
__device__ __forceinline__ int win_src_row(int r){
    int b_=r>>6, t=r&63, b=b_>>9, wid=b_&511;
    int h=(((wid>>5)<<3)+(t>>3)+SHIFT)&(HH-1);
    int w=(((wid&31)<<3)+(t&7)+SHIFT)&(WW_-1);
    return (b<<15)+(h<<8)+w;
}
__device__ __forceinline__ float warp_sum(float v){
#pragma unroll
    for(int o=16;o>0;o>>=1) v+=__shfl_xor_sync(0xffffffffu,v,o);
    return v;
}
__device__ __forceinline__ float gelu_exact(float v){ return 0.5f*v*(1.0f+erff(v*0.70710678118654752f)); }
__device__ __forceinline__ uint32_t bf2pack(float lo,float hi){
    uint32_t r; asm("cvt.rn.bf16x2.f32 %0, %1, %2;":"=r"(r):"f"(hi),"f"(lo)); return r;
}
__device__ __forceinline__ void cp_async16(uint32_t dst, const void* src){
    asm volatile("cp.async.cg.shared.global [%0], [%1], 16;"::"r"(dst),"l"(src):"memory");
}
__device__ __forceinline__ void cp_commit(){ asm volatile("cp.async.commit_group;":::"memory"); }
template<int N> __device__ __forceinline__ void cp_wait(){ asm volatile("cp.async.wait_group %0;"::"n"(N):"memory"); }

// ---------------------------------------------------------------------------
// Fused weight prep: all five [K,N]->[N,K] bf16 transposes in ONE launch.
// ---------------------------------------------------------------------------
__global__ void wt_transpose_all(const float* __restrict__ q_w, const float* __restrict__ kv_w,
                                 const float* __restrict__ proj_w, const float* __restrict__ fc1_w,
                                 const float* __restrict__ fc2_w,
                                 __nv_bfloat16* __restrict__ wq, __nv_bfloat16* __restrict__ wkv,
                                 __nv_bfloat16* __restrict__ wp, __nv_bfloat16* __restrict__ wf1,
                                 __nv_bfloat16* __restrict__ wf2){
    int i = blockIdx.x*256+threadIdx.x;
    const float* s; __nv_bfloat16* d; int K, N;
    if      (i < 36864)  { s=q_w;    d=wq;  K=CDIM;   N=CDIM;   }
    else if (i < 110592) { s=kv_w;   d=wkv; K=CDIM;   N=2*CDIM; i-=36864;  }
    else if (i < 147456) { s=proj_w; d=wp;  K=CDIM;   N=CDIM;   i-=110592; }
    else if (i < 294912) { s=fc1_w;  d=wf1; K=CDIM;   N=HIDDEN; i-=147456; }
    else if (i < 442368) { s=fc2_w;  d=wf2; K=HIDDEN; N=CDIM;   i-=294912; }
    else return;
    int n=i/K, k=i-n*K;
    d[i] = __float2bfloat16(s[(size_t)k*N+n]);
}

__global__ void ln1_gather_kernel(const float* __restrict__ x, const float* __restrict__ x1,
                                  const float* __restrict__ g, const float* __restrict__ bb,
                                  __nv_bfloat16* __restrict__ xw, __nv_bfloat16* __restrict__ x1w){
    int r=blockIdx.x, src=win_src_row(r), t=threadIdx.x;
    float v0=x[(size_t)src*CDIM+t], v1=x1[(size_t)src*CDIM+t];
    float s0=warp_sum(v0), q0=warp_sum(v0*v0), s1=warp_sum(v1), q1=warp_sum(v1*v1);
    __shared__ float red[4][6];
    int wp=t>>5, ln=t&31;
    if(ln==0){ red[0][wp]=s0; red[1][wp]=q0; red[2][wp]=s1; red[3][wp]=q1; }
    __syncthreads();
    float S0=0,Q0=0,S1=0,Q1=0;
#pragma unroll
    for(int i=0;i<6;i++){ S0+=red[0][i]; Q0+=red[1][i]; S1+=red[2][i]; Q1+=red[3][i]; }
    const float inv=1.0f/CDIM;
    float m0=S0*inv, m1=S1*inv;
    float r0=rsqrtf(Q0*inv-m0*m0+1e-5f), r1=rsqrtf(Q1*inv-m1*m1+1e-5f);
    float gg=g[t], bv=bb[t];
    xw [(size_t)r*CDIM+t]=__float2bfloat16((v0-m0)*r0*gg+bv);
    x1w[(size_t)r*CDIM+t]=__float2bfloat16((v1-m1)*r1*gg+bv);
}

__global__ void ln2_kernel(const float* __restrict__ x, const float* __restrict__ g,
                           const float* __restrict__ bb, __nv_bfloat16* __restrict__ out){
    int r=blockIdx.x, t=threadIdx.x;
    float v=x[(size_t)r*CDIM+t];
    float s=warp_sum(v), q=warp_sum(v*v);
    __shared__ float red[2][6];
    int wp=t>>5, ln=t&31;
    if(ln==0){ red[0][wp]=s; red[1][wp]=q; }
    __syncthreads();
    float S=0,Q=0;
#pragma unroll
    for(int i=0;i<6;i++){ S+=red[0][i]; Q+=red[1][i]; }
    const float inv=1.0f/CDIM;
    float m=S*inv, rs=rsqrtf(Q*inv-m*m+1e-5f);
    out[(size_t)r*CDIM+t]=__float2bfloat16((v-m)*rs*g[t]+bb[t]);
}

// ---------------------------------------------------------------------------
// Persistent-streaming HMMA bf16 GEMM: C = A @ Bw^T.  BM=128 BN=64 BK=64,
// 256 thr, 8 warps (4x2), warp tile 32x32 (R9 inner loop, measured best).
// R14: FOUR-buffer smem ring, prefetch distance 2, ONE __syncthreads per
// chunk (ring spacing makes the staged buffer disjoint from any buffer a
// lagging warp can still be reading).
// EPI: 0 bias, 1 bias+gelu, 2 bias+scatter+residual, 3 bias+residual.
// ---------------------------------------------------------------------------
#define ABUF 16384
#define BUFB 24576
#define GEMM_SMEM_BYTES (4*BUFB + 1024)

template <int EPI, int OUTBF>
__global__ __launch_bounds__(256)
void gemm_mma(const __nv_bfloat16* __restrict__ A, const __nv_bfloat16* __restrict__ Bw,
              const float* __restrict__ bias, const float* __restrict__ res,
              void* __restrict__ Cv, int M, int N, int K){
    extern __shared__ char dsm[];
    uint32_t base = (smem_u32(dsm)+1023u)&~1023u;

    int tid=threadIdx.x, lane=tid&31, wid=tid>>5;
    int wm=wid&3, wn=wid>>2;
    int Nb=N>>6, nch=K>>6;
    int ntiles=(M>>7)*Nb;

    auto stage=[&](int buf,int m0,int n0,int k0){
        uint32_t sA=base+buf*BUFB, sB=sA+ABUF;
#pragma unroll
        for(int l=0;l<4;l++){           // A: 1024 x 16B
            int i=tid+l*256, rr=i>>3, cc=i&7;
            uint32_t off=rr*128+cc*16;
            cp_async16(sA+(off^((off>>3)&0x70)), A+(size_t)(m0+rr)*K+k0+cc*8);
        }
#pragma unroll
        for(int l=0;l<2;l++){           // B: 512 x 16B
            int i=tid+l*256, rr=i>>3, cc=i&7;
            uint32_t off=rr*128+cc*16;
            cp_async16(sB+(off^((off>>3)&0x70)), Bw+(size_t)(n0+rr)*K+k0+cc*8);
        }
        cp_commit();
    };

    int t0=blockIdx.x;
    if(t0>=ntiles) return;

    // chunk-stream staging state
    int st_t=t0, st_c=0, st_buf=0;
    auto stage_next=[&](){
        if(st_t<ntiles){
            int mm=st_t/Nb, nn=st_t-mm*Nb;
            stage(st_buf, mm<<7, nn<<6, st_c<<6);
        } else cp_commit();             // uniform group count
        st_buf=(st_buf+1)&3;
        if(++st_c==nch){ st_c=0; st_t+=PGRID; }
    };

    stage_next();                       // chunk g=0 -> buf0
    stage_next();                       // chunk g=1 -> buf1
    int gbuf=0;

    for(int t=t0; t<ntiles; t+=PGRID){
        float acc[2][4][4];
#pragma unroll
        for(int a=0;a<2;a++)
#pragma unroll
            for(int b=0;b<4;b++)
#pragma unroll
                for(int c=0;c<4;c++) acc[a][b][c]=0.0f;

        for(int c=0;c<nch;c++){
            stage_next();               // chunk g+2 -> buf (g+2)&3 (safe: != g, g-1 bufs)
            cp_wait<2>();               // chunk g landed (2 younger groups pending)
            __syncthreads();            // visibility to all warps; ONLY barrier per chunk

            uint32_t sA=base+gbuf*BUFB, sB=sA+ABUF;
#pragma unroll
            for(int kk=0;kk<4;kk++){
                uint32_t af[2][4];
#pragma unroll
                for(int mt=0;mt<2;mt++){
                    int row=wm*32+mt*16+(lane&15);
                    uint32_t off=row*128+kk*32+(lane>>4)*16;
                    off^=((off>>3)&0x70);
                    asm volatile("ldmatrix.sync.aligned.m8n8.x4.shared.b16 {%0,%1,%2,%3}, [%4];"
                        :"=r"(af[mt][0]),"=r"(af[mt][1]),"=r"(af[mt][2]),"=r"(af[mt][3]):"r"(sA+off));
                }
                uint32_t bf[4][2];
#pragma unroll
                for(int nt2=0;nt2<4;nt2++){
                    int rowb=wn*32+nt2*8+(lane&7);
                    uint32_t off=rowb*128+kk*32+((lane>>3)&1)*16;
                    off^=((off>>3)&0x70);
                    asm volatile("ldmatrix.sync.aligned.m8n8.x2.shared.b16 {%0,%1}, [%2];"
                        :"=r"(bf[nt2][0]),"=r"(bf[nt2][1]):"r"(sB+off));
                }
#pragma unroll
                for(int mt=0;mt<2;mt++)
#pragma unroll
                    for(int nt2=0;nt2<4;nt2++)
                        asm volatile("mma.sync.aligned.m16n8k16.row.col.f32.bf16.bf16.f32 "
                            "{%0,%1,%2,%3}, {%4,%5,%6,%7}, {%8,%9}, {%0,%1,%2,%3};"
                            :"+f"(acc[mt][nt2][0]),"+f"(acc[mt][nt2][1]),"+f"(acc[mt][nt2][2]),"+f"(acc[mt][nt2][3])
                            :"r"(af[mt][0]),"r"(af[mt][1]),"r"(af[mt][2]),"r"(af[mt][3]),
                             "r"(bf[nt2][0]),"r"(bf[nt2][1]));
            }
            gbuf=(gbuf+1)&3;
        }

        // epilogue (no smem use; overlaps in-flight staging)
        int m0=(t/Nb)<<7, n0=(t-(t/Nb)*Nb)<<6;
#pragma unroll
        for(int mt=0;mt<2;mt++){
#pragma unroll
            for(int half=0;half<2;half++){
                int row=m0+wm*32+mt*16+(lane>>2)+half*8;
                int orow=(EPI==2)?win_src_row(row):row;
#pragma unroll
                for(int nt2=0;nt2<4;nt2++){
                    int col=n0+wn*32+nt2*8+(lane&3)*2;
                    float v0=acc[mt][nt2][half*2+0]+__ldg(bias+col);
                    float v1=acc[mt][nt2][half*2+1]+__ldg(bias+col+1);
                    if(EPI==1){ v0=gelu_exact(v0); v1=gelu_exact(v1); }
                    if(EPI==2||EPI==3){
                        const float* rp=res+(size_t)orow*N+col;
                        v0+=rp[0]; v1+=rp[1];
                    }
                    if(OUTBF){
                        *(uint32_t*)((__nv_bfloat16*)Cv+(size_t)orow*N+col)=bf2pack(v0,v1);
                    }else{
                        *(float2*)((float*)Cv+(size_t)orow*N+col)=make_float2(v0,v1);
                    }
                }
            }
        }
    }
}

// ---------------------------------------------------------------------------
// Attention: one block per window, 384 thr (6 heads x 64 rows), f32x2 FMA,
// single-pass softmax (scores tiny; mask -100 underflows exp -> 0).
// ---------------------------------------------------------------------------
#define ATTN_SMEM_BYTES 112256

__global__ __launch_bounds__(384)
void attn_kernel(const __nv_bfloat16* __restrict__ q, const __nv_bfloat16* __restrict__ kv,
                 const float* __restrict__ rpb, const float* __restrict__ mask,
                 __nv_bfloat16* __restrict__ ao){
    extern __shared__ char dsm[];
    unsigned long long* K8=(unsigned long long*)dsm;   // [64][96] f32x2
    unsigned long long* V8=K8+64*96;
    __nv_bfloat16* Ms=(__nv_bfloat16*)(V8+64*96);      // [64][66]
    float* Rp=(float*)(Ms+64*66);                      // [1350]

    int win=blockIdx.x, tid=threadIdx.x;
    const __nv_bfloat162* kvb=(const __nv_bfloat162*)(kv+(size_t)win*64*384);
    for(int i=tid;i<64*192;i+=384){
        int row=i/192, p=i-row*192;
        float2 f=__bfloat1622float2(kvb[row*192+p]);
        unsigned long long pk;
        asm("mov.b64 %0,{%1,%2};":"=l"(pk):"r"(__float_as_uint(f.x)),"r"(__float_as_uint(f.y)));
        if(p<96) K8[row*96+p]=pk; else V8[row*96+p-96]=pk;
    }
    const float* mg=mask+(size_t)(win&511)*4096;
    for(int i=tid;i<4096;i+=384) Ms[(i>>6)*66+(i&63)]=__float2bfloat16(mg[i]);
    for(int i=tid;i<1350;i+=384) Rp[i]=rpb[i];

    int h=tid/64, t=tid-h*64;
    unsigned long long q2[16];
    {
        const __nv_bfloat162* qp=(const __nv_bfloat162*)(q+((size_t)win*64+t)*CDIM+h*HDIM);
        const float sc=0.17677669529663688f;
#pragma unroll
        for(int d=0;d<16;d++){
            float2 f=__bfloat1622float2(qp[d]);
            f.x*=sc; f.y*=sc;
            asm("mov.b64 %0,{%1,%2};":"=l"(q2[d]):"r"(__float_as_uint(f.x)),"r"(__float_as_uint(f.y)));
        }
    }
    __syncthreads();

    int i1=t>>3, j1=t&7, kb=h*16;
    unsigned long long od[16];
#pragma unroll
    for(int d=0;d<16;d++) od[d]=0ULL;
    float sum=0.0f;

    for(int m=0;m<64;m++){
        const unsigned long long* kp=K8+m*96+kb;
        unsigned long long a0=0,a1=0,a2=0,a3=0;
#pragma unroll
        for(int d=0;d<16;d+=4){
            asm("fma.rn.f32x2 %0, %1, %2, %0;":"+l"(a0):"l"(q2[d+0]),"l"(kp[d+0]));
            asm("fma.rn.f32x2 %0, %1, %2, %0;":"+l"(a1):"l"(q2[d+1]),"l"(kp[d+1]));
            asm("fma.rn.f32x2 %0, %1, %2, %0;":"+l"(a2):"l"(q2[d+2]),"l"(kp[d+2]));
            asm("fma.rn.f32x2 %0, %1, %2, %0;":"+l"(a3):"l"(q2[d+3]),"l"(kp[d+3]));
        }
        uint32_t lo,hi; float s;
        asm("mov.b64 {%0,%1}, %2;":"=r"(lo),"=r"(hi):"l"(a0)); s =__uint_as_float(lo)+__uint_as_float(hi);
        asm("mov.b64 {%0,%1}, %2;":"=r"(lo),"=r"(hi):"l"(a1)); s+=__uint_as_float(lo)+__uint_as_float(hi);
        asm("mov.b64 {%0,%1}, %2;":"=r"(lo),"=r"(hi):"l"(a2)); s+=__uint_as_float(lo)+__uint_as_float(hi);
        asm("mov.b64 {%0,%1}, %2;":"=r"(lo),"=r"(hi):"l"(a3)); s+=__uint_as_float(lo)+__uint_as_float(hi);

        int ridx=(i1-(m>>3)+7)*15+(j1-(m&7)+7);
        s += Rp[ridx*6+h] + __bfloat162float(Ms[t*66+m]);
        float e=__expf(s);
        sum+=e;
        unsigned long long e2;
        asm("mov.b64 %0,{%1,%1};":"=l"(e2):"r"(__float_as_uint(e)));
        const unsigned long long* vp=V8+m*96+kb;
#pragma unroll
        for(int d=0;d<16;d++)
            asm("fma.rn.f32x2 %0, %1, %2, %0;":"+l"(od[d]):"l"(e2),"l"(vp[d]));
    }
    float inv=1.0f/sum;
    __nv_bfloat162* orow=(__nv_bfloat162*)(ao+((size_t)win*64+t)*CDIM+h*HDIM);
#pragma unroll
    for(int d=0;d<16;d++){
        uint32_t lo,hi;
        asm("mov.b64 {%0,%1}, %2;":"=r"(lo),"=r"(hi):"l"(od[d]));
        orow[d]=__floats2bfloat162_rn(__uint_as_float(lo)*inv,__uint_as_float(hi)*inv);
    }
}

extern "C" void kernel_launch(void* const* d_in, const int* in_sizes, int n_in,
                              void* d_out, int out_size){
    const float* x     =(const float*)d_in[0];
    const float* x1    =(const float*)d_in[1];
    const float* mask  =(const float*)d_in[2];
    const float* n1g   =(const float*)d_in[3];
    const float* n1b   =(const float*)d_in[4];
    const float* q_w   =(const float*)d_in[5];
    const float* q_b   =(const float*)d_in[6];
    const float* kv_w  =(const float*)d_in[7];
    const float* kv_b  =(const float*)d_in[8];
    const float* rpb   =(const float*)d_in[9];
    const float* proj_w=(const float*)d_in[10];
    const float* proj_b=(const float*)d_in[11];
    const float* n2g   =(const float*)d_in[12];
    const float* n2b   =(const float*)d_in[13];
    const float* fc1_w =(const float*)d_in[14];
    const float* fc1_b =(const float*)d_in[15];
    const float* fc2_w =(const float*)d_in[16];
    const float* fc2_b =(const float*)d_in[17];

    __nv_bfloat16 *xw,*x1w,*qb,*kvb,*ao,*xn2,*hb,*wq,*wkv,*wp,*wf1,*wf2;
    float* xo;
    cudaGetSymbolAddress((void**)&xw, g_xw);  cudaGetSymbolAddress((void**)&x1w,g_x1w);
    cudaGetSymbolAddress((void**)&qb, g_qb);  cudaGetSymbolAddress((void**)&kvb,g_kvb);
    cudaGetSymbolAddress((void**)&ao, g_ao);  cudaGetSymbolAddress((void**)&xo, g_xo);
    cudaGetSymbolAddress((void**)&xn2,g_xn2); cudaGetSymbolAddress((void**)&hb, g_hb);
    cudaGetSymbolAddress((void**)&wq, g_wq);  cudaGetSymbolAddress((void**)&wkv,g_wkv);
    cudaGetSymbolAddress((void**)&wp, g_wp);  cudaGetSymbolAddress((void**)&wf1,g_wf1);
    cudaGetSymbolAddress((void**)&wf2,g_wf2);

    cudaFuncSetAttribute(gemm_mma<0,1>, cudaFuncAttributeMaxDynamicSharedMemorySize, GEMM_SMEM_BYTES);
    cudaFuncSetAttribute(gemm_mma<1,1>, cudaFuncAttributeMaxDynamicSharedMemorySize, GEMM_SMEM_BYTES);
    cudaFuncSetAttribute(gemm_mma<2,0>, cudaFuncAttributeMaxDynamicSharedMemorySize, GEMM_SMEM_BYTES);
    cudaFuncSetAttribute(gemm_mma<3,0>, cudaFuncAttributeMaxDynamicSharedMemorySize, GEMM_SMEM_BYTES);
    cudaFuncSetAttribute(attn_kernel,   cudaFuncAttributeMaxDynamicSharedMemorySize, ATTN_SMEM_BYTES);

    wt_transpose_all<<<(442368+255)/256,256>>>(q_w, kv_w, proj_w, fc1_w, fc2_w,
                                               wq, wkv, wp, wf1, wf2);

    ln1_gather_kernel<<<MROWS, CDIM>>>(x, x1, n1g, n1b, xw, x1w);

    gemm_mma<0,1><<<PGRID, 256, GEMM_SMEM_BYTES>>>(x1w, wq,  q_b,  nullptr, qb,  MROWS, CDIM,   CDIM);
    gemm_mma<0,1><<<PGRID, 256, GEMM_SMEM_BYTES>>>(xw,  wkv, kv_b, nullptr, kvb, MROWS, 2*CDIM, CDIM);

    attn_kernel<<<2048, 384, ATTN_SMEM_BYTES>>>(qb, kvb, rpb, mask, ao);

    gemm_mma<2,0><<<PGRID, 256, GEMM_SMEM_BYTES>>>(ao,  wp,  proj_b, x,  xo, MROWS, CDIM, CDIM);

    ln2_kernel<<<MROWS, CDIM>>>(xo, n2g, n2b, xn2);

    gemm_mma<1,1><<<PGRID, 256, GEMM_SMEM_BYTES>>>(xn2, wf1, fc1_b, nullptr, hb, MROWS, HIDDEN, CDIM);
    gemm_mma<3,0><<<PGRID, 256, GEMM_SMEM_BYTES>>>(hb,  wf2, fc2_b, xo, (float*)d_out, MROWS, CDIM, HIDDEN);
}